// round 11
// baseline (speedup 1.0000x reference)
#include <cuda_runtime.h>

// ZNCC fused, warp-per-channel sliding windows, 4 columns/lane (float4 I/O).
// CTA = 96 threads = 3 warps; warp w handles channel w of one
// (batch, strip, col-group) tile: 128 raw cols (4/lane) x 32 output rows.
// Horizontal 5-sums: 4 shuffles per signal serve 4 columns.
// Per-channel NCC rows -> smem plane; one __syncthreads; fixed-order combine.
//
// math per pixel (zero-padded 5x5 means):
//   mx = box(x), my = box(y); xc = x-mx, yc = y-my (forced 0 outside image)
//   ncc = Sxy / (sqrt(Sxx*Syy) + 25e-8),  S* = 5x5 sums of products
//   out = mean_c(ncc)

#define HH 512
#define WW 512
#define CHAN 3
#define SSTRIP 32
#define NSTRIPS (HH / SSTRIP)          // 16
#define OUTCOLS 120
#define NGROUPS 5                      // 5*120 = 600 >= 512
#define NBATCH 16
#define NCTAS (NGROUPS * NSTRIPS * NBATCH)   // 1280
#define PSTRIDE 124                    // plane row stride (mult of 4 -> float4)

// CINT: all 128 raw columns inside image (groups 1..3)
// RINT: all raw rows r0-4 .. r0+35 inside image (strips 1..14)
template<bool CINT, bool RINT>
__device__ __forceinline__ void zncc_tile(
    const float* __restrict__ xb, const float* __restrict__ yb,
    float (*plane)[PSTRIDE],
    int r0, float m0, float m1, float m2, float m3,
    bool outLane, int gc_c, int pcol)
{
    const unsigned FULL = 0xFFFFFFFFu;
    const float inv25 = 1.0f / 25.0f;

    // ring buffers (indices static after unroll-by-5)
    float rhx[4][5], rhy[4][5];
    float rqxy[4][5], rqxx[4][5], rqyy[4][5];
    #pragma unroll
    for (int j = 0; j < 4; j++)
        #pragma unroll
        for (int i = 0; i < 5; i++) {
            rhx[j][i] = rhy[j][i] = 0.f;
            rqxy[j][i] = rqxx[j][i] = rqyy[j][i] = 0.f;
        }
    float sHx[4] = {0.f,0.f,0.f,0.f}, sHy[4] = {0.f,0.f,0.f,0.f};
    float sQxy[4] = {0.f,0.f,0.f,0.f}, sQxx[4] = {0.f,0.f,0.f,0.f}, sQyy[4] = {0.f,0.f,0.f,0.f};
    // 2-deep shift pipeline for raw center values (need row t-2 at step t)
    float px1[4] = {0.f,0.f,0.f,0.f}, px2[4] = {0.f,0.f,0.f,0.f};
    float py1[4] = {0.f,0.f,0.f,0.f}, py2[4] = {0.f,0.f,0.f,0.f};

    // staged next-row values (software prefetch)
    float4 nvx = make_float4(0.f,0.f,0.f,0.f), nvy = make_float4(0.f,0.f,0.f,0.f);
    {
        const int t0 = r0 - 4;
        if (RINT || t0 >= 0) {
            nvx = *(const float4*)(xb + (size_t)t0 * WW + gc_c);
            nvy = *(const float4*)(yb + (size_t)t0 * WW + gc_c);
        }
    }

    for (int sb = 0; sb < SSTRIP + 8; sb += 5) {
        #pragma unroll
        for (int k = 0; k < 5; k++) {
            const int s = sb + k;                 // s % 5 == k
            const int t = r0 - 4 + s;             // raw row consumed now

            // ---- consume staged row t, issue loads for row t+1 ----
            float vx0, vx1, vx2, vx3, vy0, vy1, vy2, vy3;
            if (CINT) {
                vx0 = nvx.x; vx1 = nvx.y; vx2 = nvx.z; vx3 = nvx.w;
                vy0 = nvy.x; vy1 = nvy.y; vy2 = nvy.z; vy3 = nvy.w;
            } else {
                vx0 = nvx.x * m0; vx1 = nvx.y * m1; vx2 = nvx.z * m2; vx3 = nvx.w * m3;
                vy0 = nvy.x * m0; vy1 = nvy.y * m1; vy2 = nvy.z * m2; vy3 = nvy.w * m3;
            }
            {
                const int tn = t + 1;             // warp-uniform
                if (RINT || (unsigned)tn < (unsigned)HH) {
                    nvx = *(const float4*)(xb + (size_t)tn * WW + gc_c);
                    nvy = *(const float4*)(yb + (size_t)tn * WW + gc_c);
                } else {
                    nvx = make_float4(0.f,0.f,0.f,0.f);
                    nvy = make_float4(0.f,0.f,0.f,0.f);
                }
            }
            if (!RINT) {
                if (t < 0) {
                    vx0 = vx1 = vx2 = vx3 = 0.f;
                    vy0 = vy1 = vy2 = vy3 = 0.f;
                }
            }

            // ---- horizontal 5-sums of x,y: 4 shuffles per signal ----
            float um2x = __shfl_up_sync(FULL, vx2, 1);    // col -2
            float um3x = __shfl_up_sync(FULL, vx3, 1);    // col -1
            float dp0x = __shfl_down_sync(FULL, vx0, 1);  // col +4
            float dp1x = __shfl_down_sync(FULL, vx1, 1);  // col +5
            float c01x = vx0 + vx1, c23x = vx2 + vx3;
            float c03x = c01x + c23x;
            float hx0 = (um2x + um3x) + c01x + vx2;
            float hx1 = um3x + c03x;
            float hx2 = c03x + dp0x;
            float hx3 = (c23x + vx1) + (dp0x + dp1x);

            float um2y = __shfl_up_sync(FULL, vy2, 1);
            float um3y = __shfl_up_sync(FULL, vy3, 1);
            float dp0y = __shfl_down_sync(FULL, vy0, 1);
            float dp1y = __shfl_down_sync(FULL, vy1, 1);
            float c01y = vy0 + vy1, c23y = vy2 + vy3;
            float c03y = c01y + c23y;
            float hy0 = (um2y + um3y) + c01y + vy2;
            float hy1 = um3y + c03y;
            float hy2 = c03y + dp0y;
            float hy3 = (c23y + vy1) + (dp0y + dp1y);

            // ---- vertical sliding sums of h ----
            sHx[0] += hx0 - rhx[0][k]; rhx[0][k] = hx0;
            sHx[1] += hx1 - rhx[1][k]; rhx[1][k] = hx1;
            sHx[2] += hx2 - rhx[2][k]; rhx[2][k] = hx2;
            sHx[3] += hx3 - rhx[3][k]; rhx[3][k] = hx3;
            sHy[0] += hy0 - rhy[0][k]; rhy[0][k] = hy0;
            sHy[1] += hy1 - rhy[1][k]; rhy[1][k] = hy1;
            sHy[2] += hy2 - rhy[2][k]; rhy[2][k] = hy2;
            sHy[3] += hy3 - rhy[3][k]; rhy[3][k] = hy3;

            if (s >= 4) {
                // centered values at row tm = t-2 (raw from 2 steps ago)
                float xc0, xc1, xc2, xc3, yc0, yc1, yc2, yc3;
                if (CINT && RINT) {
                    xc0 = fmaf(sHx[0], -inv25, px2[0]);
                    xc1 = fmaf(sHx[1], -inv25, px2[1]);
                    xc2 = fmaf(sHx[2], -inv25, px2[2]);
                    xc3 = fmaf(sHx[3], -inv25, px2[3]);
                    yc0 = fmaf(sHy[0], -inv25, py2[0]);
                    yc1 = fmaf(sHy[1], -inv25, py2[1]);
                    yc2 = fmaf(sHy[2], -inv25, py2[2]);
                    yc3 = fmaf(sHy[3], -inv25, py2[3]);
                } else {
                    const int tm = t - 2;
                    const float rm = (RINT || ((unsigned)tm < (unsigned)HH)) ? 1.0f : 0.0f;
                    const float f0 = CINT ? rm : m0 * rm;
                    const float f1 = CINT ? rm : m1 * rm;
                    const float f2 = CINT ? rm : m2 * rm;
                    const float f3 = CINT ? rm : m3 * rm;
                    xc0 = fmaf(sHx[0], -inv25, px2[0]) * f0;
                    xc1 = fmaf(sHx[1], -inv25, px2[1]) * f1;
                    xc2 = fmaf(sHx[2], -inv25, px2[2]) * f2;
                    xc3 = fmaf(sHx[3], -inv25, px2[3]) * f3;
                    yc0 = fmaf(sHy[0], -inv25, py2[0]) * f0;
                    yc1 = fmaf(sHy[1], -inv25, py2[1]) * f1;
                    yc2 = fmaf(sHy[2], -inv25, py2[2]) * f2;
                    yc3 = fmaf(sHy[3], -inv25, py2[3]) * f3;
                }

                // neighbors of xc,yc (4 shuffles per signal)
                float xm2 = __shfl_up_sync(FULL, xc2, 1);
                float xm1 = __shfl_up_sync(FULL, xc3, 1);
                float xp4 = __shfl_down_sync(FULL, xc0, 1);
                float xp5 = __shfl_down_sync(FULL, xc1, 1);
                float ym2 = __shfl_up_sync(FULL, yc2, 1);
                float ym1 = __shfl_up_sync(FULL, yc3, 1);
                float yp4 = __shfl_down_sync(FULL, yc0, 1);
                float yp5 = __shfl_down_sync(FULL, yc1, 1);

                // horizontal 5-sums of products for 4 cols (per type)
                #define QSUMS(q0, q1, q2, q3, A_m2, A_m1, A0, A1, A2, A3, A4, A5,   \
                              B_m2, B_m1, B0, B1, B2, B3, B4, B5)                   \
                {                                                                   \
                    float Pm2 = (A_m2) * (B_m2), Pm1 = (A_m1) * (B_m1);             \
                    float P0 = (A0)*(B0), P1 = (A1)*(B1), P2 = (A2)*(B2);           \
                    float P3 = (A3)*(B3), P4 = (A4)*(B4), P5 = (A5)*(B5);           \
                    float s12 = P1 + P2;                                            \
                    float t02 = P0 + s12;                                           \
                    float c03 = t02 + P3;                                           \
                    q0 = (Pm2 + Pm1) + t02;                                         \
                    q1 = Pm1 + c03;                                                 \
                    q2 = c03 + P4;                                                  \
                    q3 = (s12 + P3) + (P4 + P5);                                    \
                }
                float qxy0, qxy1, qxy2, qxy3;
                QSUMS(qxy0, qxy1, qxy2, qxy3,
                      xm2, xm1, xc0, xc1, xc2, xc3, xp4, xp5,
                      ym2, ym1, yc0, yc1, yc2, yc3, yp4, yp5);
                float qxx0, qxx1, qxx2, qxx3;
                QSUMS(qxx0, qxx1, qxx2, qxx3,
                      xm2, xm1, xc0, xc1, xc2, xc3, xp4, xp5,
                      xm2, xm1, xc0, xc1, xc2, xc3, xp4, xp5);
                float qyy0, qyy1, qyy2, qyy3;
                QSUMS(qyy0, qyy1, qyy2, qyy3,
                      ym2, ym1, yc0, yc1, yc2, yc3, yp4, yp5,
                      ym2, ym1, yc0, yc1, yc2, yc3, yp4, yp5);
                #undef QSUMS

                // vertical sliding sums of q
                sQxy[0] += qxy0 - rqxy[0][k]; rqxy[0][k] = qxy0;
                sQxy[1] += qxy1 - rqxy[1][k]; rqxy[1][k] = qxy1;
                sQxy[2] += qxy2 - rqxy[2][k]; rqxy[2][k] = qxy2;
                sQxy[3] += qxy3 - rqxy[3][k]; rqxy[3][k] = qxy3;
                sQxx[0] += qxx0 - rqxx[0][k]; rqxx[0][k] = qxx0;
                sQxx[1] += qxx1 - rqxx[1][k]; rqxx[1][k] = qxx1;
                sQxx[2] += qxx2 - rqxx[2][k]; rqxx[2][k] = qxx2;
                sQxx[3] += qxx3 - rqxx[3][k]; rqxx[3][k] = qxx3;
                sQyy[0] += qyy0 - rqyy[0][k]; rqyy[0][k] = qyy0;
                sQyy[1] += qyy1 - rqyy[1][k]; rqyy[1][k] = qyy1;
                sQyy[2] += qyy2 - rqyy[2][k]; rqyy[2][k] = qyy2;
                sQyy[3] += qyy3 - rqyy[3][k]; rqyy[3][k] = qyy3;

                if (s >= 8) {
                    const int row = s - 8;        // output row within strip
                    float4 n;
                    {
                        float d0 = sqrtf(fmaxf(sQxx[0] * sQyy[0], 0.f)) + 2.5e-7f;
                        float d1 = sqrtf(fmaxf(sQxx[1] * sQyy[1], 0.f)) + 2.5e-7f;
                        float d2 = sqrtf(fmaxf(sQxx[2] * sQyy[2], 0.f)) + 2.5e-7f;
                        float d3 = sqrtf(fmaxf(sQxx[3] * sQyy[3], 0.f)) + 2.5e-7f;
                        n.x = __fdividef(sQxy[0], d0);
                        n.y = __fdividef(sQxy[1], d1);
                        n.z = __fdividef(sQxy[2], d2);
                        n.w = __fdividef(sQxy[3], d3);
                    }
                    if (outLane) {
                        *(float4*)&plane[row][pcol] = n;
                    }
                }
            }

            // shift raw-center pipeline
            px2[0] = px1[0]; px1[0] = vx0;
            px2[1] = px1[1]; px1[1] = vx1;
            px2[2] = px1[2]; px1[2] = vx2;
            px2[3] = px1[3]; px1[3] = vx3;
            py2[0] = py1[0]; py1[0] = vy0;
            py2[1] = py1[1]; py1[1] = vy1;
            py2[2] = py1[2]; py1[2] = vy2;
            py2[3] = py1[3]; py1[3] = vy3;
        }
    }
}

__global__ __launch_bounds__(96, 4)
void zncc_warp_kernel(const float* __restrict__ xg,
                      const float* __restrict__ yg,
                      float* __restrict__ outg)
{
    __shared__ float plane[CHAN][SSTRIP][PSTRIDE];

    const int tid  = threadIdx.x;
    const int lane = tid & 31;
    const int ch   = tid >> 5;          // warp id == channel

    const int task  = blockIdx.x;
    const int b     = task / (NGROUPS * NSTRIPS);
    const int rem   = task - b * (NGROUPS * NSTRIPS);
    const int strip = rem / NGROUPS;
    const int g     = rem - strip * NGROUPS;

    const int r0  = strip * SSTRIP;
    const int gc0 = g * OUTCOLS - 4 + 4 * lane;   // first raw col (mult of 4)
    const float m0 = ((unsigned)(gc0 + 0) < (unsigned)WW) ? 1.0f : 0.0f;
    const float m1 = ((unsigned)(gc0 + 1) < (unsigned)WW) ? 1.0f : 0.0f;
    const float m2 = ((unsigned)(gc0 + 2) < (unsigned)WW) ? 1.0f : 0.0f;
    const float m3 = ((unsigned)(gc0 + 3) < (unsigned)WW) ? 1.0f : 0.0f;
    const bool outLane = (lane >= 1) && (lane <= 30) &&
                         (g * OUTCOLS + 4 * (lane - 1) < WW);
    const int gc_c = min(max(gc0, 0), WW - 4);    // clamped, float4-aligned
    const int pcol = 4 * (lane - 1);              // plane column base

    const float inv3 = 1.0f / 3.0f;

    const float* xb = xg + (size_t)(b * CHAN + ch) * (HH * WW);
    const float* yb = yg + (size_t)(b * CHAN + ch) * (HH * WW);

    // interior flags (uniform per CTA)
    const bool cint = (g >= 1) && (g <= 3);                // all 128 cols in-image
    const bool rint = (strip >= 1) && (strip <= NSTRIPS - 2);

    if (cint) {
        if (rint) zncc_tile<true,  true >(xb, yb, plane[ch], r0, m0, m1, m2, m3, outLane, gc_c, pcol);
        else      zncc_tile<true,  false>(xb, yb, plane[ch], r0, m0, m1, m2, m3, outLane, gc_c, pcol);
    } else {
        if (rint) zncc_tile<false, true >(xb, yb, plane[ch], r0, m0, m1, m2, m3, outLane, gc_c, pcol);
        else      zncc_tile<false, false>(xb, yb, plane[ch], r0, m0, m1, m2, m3, outLane, gc_c, pcol);
    }

    __syncthreads();

    // ---- combine channels in fixed order (deterministic), float4 I/O ----
    float* outp = outg + (size_t)b * (HH * WW) + (size_t)r0 * WW + g * OUTCOLS;
    for (int idx = tid; idx < SSTRIP * (OUTCOLS / 4); idx += 96) {
        int row = idx / (OUTCOLS / 4);
        int c4  = idx - row * (OUTCOLS / 4);
        int col = 4 * c4;
        if (g * OUTCOLS + col < WW) {   // col mult of 4, WW mult of 4 -> full float4 in
            float4 p0 = *(const float4*)&plane[0][row][col];
            float4 p1 = *(const float4*)&plane[1][row][col];
            float4 p2 = *(const float4*)&plane[2][row][col];
            float4 v;
            v.x = (p0.x + p1.x + p2.x) * inv3;
            v.y = (p0.y + p1.y + p2.y) * inv3;
            v.z = (p0.z + p1.z + p2.z) * inv3;
            v.w = (p0.w + p1.w + p2.w) * inv3;
            *(float4*)&outp[(size_t)row * WW + col] = v;
        }
    }
}

extern "C" void kernel_launch(void* const* d_in, const int* in_sizes, int n_in,
                              void* d_out, int out_size)
{
    const float* x = (const float*)d_in[0];
    const float* y = (const float*)d_in[1];
    float* out = (float*)d_out;

    zncc_warp_kernel<<<NCTAS, 96>>>(x, y, out);
}

// round 12
// speedup vs baseline: 1.3049x; 1.3049x over previous
#include <cuda_runtime.h>

// ZNCC fused, warp-per-channel sliding-window (R10 structure) with register
// diet: (a) vertical product sums computed directly from the 5-entry rings at
// output time (drops 6 accumulators), (b) raw center row re-loaded from L1 at
// a -3*WW offset instead of a 2-deep register shift pipeline (drops 8 regs).
// -> fits 9 CTAs/SM (27 warps), grid runs in <2 waves.
// CTA = 96 threads = 3 warps; warp w handles channel w of one
// (batch, strip, col-group) tile: 64 raw cols (2/lane) x 32 output rows.
//
// math per pixel (zero-padded 5x5 means):
//   mx = box(x), my = box(y); xc = x-mx, yc = y-my (forced 0 outside image)
//   ncc = Sxy / (sqrt(Sxx*Syy) + 25e-8),  S* = 5x5 sums of products
//   out = mean_c(ncc)

#define HH 512
#define WW 512
#define CHAN 3
#define SSTRIP 32
#define NSTRIPS (HH / SSTRIP)          // 16
#define OUTCOLS 56
#define NGROUPS 10                     // 10*56 = 560 >= 512
#define NBATCH 16
#define NCTAS (NGROUPS * NSTRIPS * NBATCH)   // 2560
#define PSTRIDE 58                     // plane row stride (even -> float2 ops)

// CINT: all 64 raw columns inside image (groups 1..8)
// RINT: all raw rows r0-4 .. r0+35 inside image (strips 1..14)
template<bool CINT, bool RINT>
__device__ __forceinline__ void zncc_tile(
    const float* __restrict__ xb, const float* __restrict__ yb,
    float (*plane)[PSTRIDE],
    int r0, int lane, float mA, float mB, bool outLane, int gca_c, int pcol)
{
    const unsigned FULL = 0xFFFFFFFFu;
    const float inv25 = 1.0f / 25.0f;

    // ring buffers (indices static after unroll-by-5)
    float hxA[5], hxB[5], hyA[5], hyB[5];
    float qxyA[5], qxyB[5], qxxA[5], qxxB[5], qyyA[5], qyyB[5];
    #pragma unroll
    for (int i = 0; i < 5; i++) {
        hxA[i] = hxB[i] = hyA[i] = hyB[i] = 0.f;
        qxyA[i] = qxyB[i] = qxxA[i] = qxxB[i] = qyyA[i] = qyyB[i] = 0.f;
    }
    float sHxA = 0.f, sHxB = 0.f, sHyA = 0.f, sHyB = 0.f;

    // staged next-row values (software prefetch)
    float2 nvx = make_float2(0.f, 0.f), nvy = make_float2(0.f, 0.f);
    {
        const int t0 = r0 - 4;
        if (RINT || t0 >= 0) {
            nvx = *(const float2*)(xb + (size_t)t0 * WW + gca_c);
            nvy = *(const float2*)(yb + (size_t)t0 * WW + gca_c);
        }
    }

    for (int sb = 0; sb < SSTRIP + 8; sb += 5) {
        #pragma unroll
        for (int k = 0; k < 5; k++) {
            const int s = sb + k;                 // s % 5 == k
            const int t = r0 - 4 + s;             // raw row consumed now
            const int tn = t + 1;                 // prefetch target row

            // base address of row tn (used by prefetch and center reload)
            const float* xrow = xb + (size_t)tn * WW + gca_c;
            const float* yrow = yb + (size_t)tn * WW + gca_c;

            // ---- center row (t-2) reload: L1-resident (loaded 3 steps ago)
            float2 cvx, cvy;
            if (RINT) {
                // t-2 = tn-3 always in [0,HH) for interior strips
                cvx = *(const float2*)(xrow - 3 * WW);
                cvy = *(const float2*)(yrow - 3 * WW);
            } else {
                const int tcl = min(max(t - 2, 0), HH - 1);
                cvx = *(const float2*)(xb + (size_t)tcl * WW + gca_c);
                cvy = *(const float2*)(yb + (size_t)tcl * WW + gca_c);
            }

            // ---- consume staged row t, issue loads for row t+1 ----
            float vxA, vxB, vyA, vyB;
            if (CINT) {
                vxA = nvx.x; vxB = nvx.y;
                vyA = nvy.x; vyB = nvy.y;
            } else {
                vxA = nvx.x * mA; vxB = nvx.y * mB;
                vyA = nvy.x * mA; vyB = nvy.y * mB;
            }
            if (RINT || (unsigned)tn < (unsigned)HH) {
                nvx = *(const float2*)xrow;
                nvy = *(const float2*)yrow;
            } else {
                nvx = make_float2(0.f, 0.f);
                nvy = make_float2(0.f, 0.f);
            }
            if (!RINT) {
                if (t < 0) { vxA = vxB = vyA = vyB = 0.f; }  // above-image rows
            }

            // ---- horizontal 5-sums of x,y via shuffles ----
            float vxAm = __shfl_up_sync(FULL, vxA, 1);
            float vxBm = __shfl_up_sync(FULL, vxB, 1);
            float vxAp = __shfl_down_sync(FULL, vxA, 1);
            float vxBp = __shfl_down_sync(FULL, vxB, 1);
            float cx   = vxBm + vxA + vxB + vxAp;
            float hxEn = cx + vxAm;               // col A (2l)
            float hxOn = cx + vxBp;               // col B (2l+1)

            float vyAm = __shfl_up_sync(FULL, vyA, 1);
            float vyBm = __shfl_up_sync(FULL, vyB, 1);
            float vyAp = __shfl_down_sync(FULL, vyA, 1);
            float vyBp = __shfl_down_sync(FULL, vyB, 1);
            float cy   = vyBm + vyA + vyB + vyAp;
            float hyEn = cy + vyAm;
            float hyOn = cy + vyBp;

            // ---- vertical sliding sums of h ----
            sHxA += hxEn - hxA[k]; hxA[k] = hxEn;
            sHxB += hxOn - hxB[k]; hxB[k] = hxOn;
            sHyA += hyEn - hyA[k]; hyA[k] = hyEn;
            sHyB += hyOn - hyB[k]; hyB[k] = hyOn;

            if (s >= 4) {
                // centered values at row tm = t-2 (center from L1 reload)
                float xcA, xcB, ycA, ycB;
                if (CINT && RINT) {
                    xcA = fmaf(sHxA, -inv25, cvx.x);
                    xcB = fmaf(sHxB, -inv25, cvx.y);
                    ycA = fmaf(sHyA, -inv25, cvy.x);
                    ycB = fmaf(sHyB, -inv25, cvy.y);
                } else {
                    const int tm = t - 2;
                    const float rm = (RINT || ((unsigned)tm < (unsigned)HH)) ? 1.0f : 0.0f;
                    const float fmA = CINT ? rm : mA * rm;
                    const float fmB = CINT ? rm : mB * rm;
                    xcA = fmaf(sHxA, -inv25, cvx.x) * fmA;
                    xcB = fmaf(sHxB, -inv25, cvx.y) * fmB;
                    ycA = fmaf(sHyA, -inv25, cvy.x) * fmA;
                    ycB = fmaf(sHyB, -inv25, cvy.y) * fmB;
                }

                // neighbors of xc,yc
                float xcAm = __shfl_up_sync(FULL, xcA, 1);
                float xcBm = __shfl_up_sync(FULL, xcB, 1);
                float xcAp = __shfl_down_sync(FULL, xcA, 1);
                float xcBp = __shfl_down_sync(FULL, xcB, 1);
                float ycAm = __shfl_up_sync(FULL, ycA, 1);
                float ycBm = __shfl_up_sync(FULL, ycB, 1);
                float ycAp = __shfl_down_sync(FULL, ycA, 1);
                float ycBp = __shfl_down_sync(FULL, ycB, 1);

                // horizontal 5-sums of products (shared middle-4 term)
                float c4xy = xcBm * ycBm + xcA * ycA + xcB * ycB + xcAp * ycAp;
                qxyA[k] = c4xy + xcAm * ycAm;
                qxyB[k] = c4xy + xcBp * ycBp;
                float c4xx = xcBm * xcBm + xcA * xcA + xcB * xcB + xcAp * xcAp;
                qxxA[k] = c4xx + xcAm * xcAm;
                qxxB[k] = c4xx + xcBp * xcBp;
                float c4yy = ycBm * ycBm + ycA * ycA + ycB * ycB + ycAp * ycAp;
                qyyA[k] = c4yy + ycAm * ycAm;
                qyyB[k] = c4yy + ycBp * ycBp;

                if (s >= 8) {
                    // direct 5-term vertical sums from the rings
                    float Sxy_A = ((qxyA[0] + qxyA[1]) + (qxyA[2] + qxyA[3])) + qxyA[4];
                    float Sxy_B = ((qxyB[0] + qxyB[1]) + (qxyB[2] + qxyB[3])) + qxyB[4];
                    float Sxx_A = ((qxxA[0] + qxxA[1]) + (qxxA[2] + qxxA[3])) + qxxA[4];
                    float Sxx_B = ((qxxB[0] + qxxB[1]) + (qxxB[2] + qxxB[3])) + qxxB[4];
                    float Syy_A = ((qyyA[0] + qyyA[1]) + (qyyA[2] + qyyA[3])) + qyyA[4];
                    float Syy_B = ((qyyB[0] + qyyB[1]) + (qyyB[2] + qyyB[3])) + qyyB[4];

                    const int row = s - 8;        // output row within strip
                    float dA = sqrtf(fmaxf(Sxx_A * Syy_A, 0.f)) + 2.5e-7f;
                    float dB = sqrtf(fmaxf(Sxx_B * Syy_B, 0.f)) + 2.5e-7f;
                    float nA = __fdividef(Sxy_A, dA);
                    float nB = __fdividef(Sxy_B, dB);
                    if (outLane) {
                        *(float2*)&plane[row][pcol] = make_float2(nA, nB);
                    }
                }
            }
        }
    }
}

__global__ __launch_bounds__(96, 9)
void zncc_warp_kernel(const float* __restrict__ xg,
                      const float* __restrict__ yg,
                      float* __restrict__ outg)
{
    __shared__ float plane[CHAN][SSTRIP][PSTRIDE];

    const int tid  = threadIdx.x;
    const int lane = tid & 31;
    const int ch   = tid >> 5;          // warp id == channel

    const int task  = blockIdx.x;
    const int b     = task / (NGROUPS * NSTRIPS);
    const int rem   = task - b * (NGROUPS * NSTRIPS);
    const int strip = rem / NGROUPS;
    const int g     = rem - strip * NGROUPS;

    const int r0  = strip * SSTRIP;
    const int gcA = g * OUTCOLS - 4 + 2 * lane;   // even
    const int gcB = gcA + 1;
    const float mA = (gcA >= 0 && gcA < WW) ? 1.0f : 0.0f;
    const float mB = (gcB >= 0 && gcB < WW) ? 1.0f : 0.0f;
    const bool outLane = (lane >= 2) && (lane <= 29) && (gcA < WW);
    const int gca_c = min(max(gcA, 0), WW - 2);   // clamped, float2-safe
    const int pcol  = 2 * lane - 4;               // plane column for col A

    const float inv3 = 1.0f / 3.0f;

    const float* xb = xg + (size_t)(b * CHAN + ch) * (HH * WW);
    const float* yb = yg + (size_t)(b * CHAN + ch) * (HH * WW);

    // interior flags (uniform per CTA)
    const bool cint = (g >= 1) && (g <= 8);               // all 64 cols in-image
    const bool rint = (strip >= 1) && (strip <= NSTRIPS - 2);  // all rows in-image

    if (cint) {
        if (rint) zncc_tile<true,  true >(xb, yb, plane[ch], r0, lane, mA, mB, outLane, gca_c, pcol);
        else      zncc_tile<true,  false>(xb, yb, plane[ch], r0, lane, mA, mB, outLane, gca_c, pcol);
    } else {
        if (rint) zncc_tile<false, true >(xb, yb, plane[ch], r0, lane, mA, mB, outLane, gca_c, pcol);
        else      zncc_tile<false, false>(xb, yb, plane[ch], r0, lane, mA, mB, outLane, gca_c, pcol);
    }

    __syncthreads();

    // ---- combine channels in fixed order (deterministic), float2 I/O ----
    float* outp = outg + (size_t)b * (HH * WW) + (size_t)r0 * WW + g * OUTCOLS;
    for (int idx = tid; idx < SSTRIP * (OUTCOLS / 2); idx += 96) {
        int row = idx / (OUTCOLS / 2);
        int c2  = idx - row * (OUTCOLS / 2);
        int col = 2 * c2;
        if (g * OUTCOLS + col < WW) {   // col even, WW even -> col+1 also in
            float2 p0 = *(const float2*)&plane[0][row][col];
            float2 p1 = *(const float2*)&plane[1][row][col];
            float2 p2 = *(const float2*)&plane[2][row][col];
            float2 v;
            v.x = (p0.x + p1.x + p2.x) * inv3;
            v.y = (p0.y + p1.y + p2.y) * inv3;
            *(float2*)&outp[(size_t)row * WW + col] = v;
        }
    }
}

extern "C" void kernel_launch(void* const* d_in, const int* in_sizes, int n_in,
                              void* d_out, int out_size)
{
    const float* x = (const float*)d_in[0];
    const float* y = (const float*)d_in[1];
    float* out = (float*)d_out;

    zncc_warp_kernel<<<NCTAS, 96>>>(x, y, out);
}